// round 3
// baseline (speedup 1.0000x reference)
#include <cuda_runtime.h>
#include <cuda_bf16.h>
#include <math.h>

// ---------------------------------------------------------------------------
// Problem constants (shapes fixed by the dataset; buffers sized with headroom)
// ---------------------------------------------------------------------------
#define F 128                  // feature width (F_IN == F_HID == 128)
#define MAXN 102400            // >= 100000, multiple of 1024
#define MAXE 1700000           // >= 1600000
#define NCHUNK_MAX 128         // MAXN/1024 <= 128

// ---------------------------------------------------------------------------
// Device scratch (static globals: allowed; runtime allocation is not)
// ---------------------------------------------------------------------------
__device__ float g_bufA[(size_t)MAXN * F];   // 52.4 MB
__device__ float g_bufB[(size_t)MAXN * F];   // 52.4 MB
__device__ float g_dis[MAXN];                // deg^{-1/2}
__device__ float g_scalar[MAXN];             // layer-3 per-node scalar
__device__ int   g_count[MAXN];
__device__ int   g_cursor[MAXN];
__device__ int   g_offsets[MAXN + 1];
__device__ int   g_csr_src[MAXE];
__device__ int   g_chunk[NCHUNK_MAX];
__device__ int   g_chunkbase[NCHUNK_MAX];

// ---------------------------------------------------------------------------
// Preprocessing: degree, rsqrt, CSR build
// ---------------------------------------------------------------------------
__global__ void zero_kernel(int n, int e) {
    int i = blockIdx.x * blockDim.x + threadIdx.x;
    if (i < n) { g_count[i] = 0; g_cursor[i] = 0; }
    if (i == 0) g_offsets[n] = e;   // constant; scan only writes idx < n
}

__global__ void count_kernel(const int* __restrict__ dst, int e) {
    int i = blockIdx.x * blockDim.x + threadIdx.x;
    if (i < e) atomicAdd(&g_count[dst[i]], 1);
}

__global__ void dis_kernel(int n) {
    int i = blockIdx.x * blockDim.x + threadIdx.x;
    if (i < n) g_dis[i] = rsqrtf((float)(g_count[i] + 1));  // +1 self-loop
}

// chunk = 1024 elements, block = 256 threads (4 elems/thread)
__global__ void scan1_kernel(int n) {
    __shared__ int sh[256];
    int b = blockIdx.x, t = threadIdx.x;
    int base = b * 1024 + t * 4;
    int s = 0;
#pragma unroll
    for (int j = 0; j < 4; j++) {
        int idx = base + j;
        if (idx < n) s += g_count[idx];
    }
    sh[t] = s;
    __syncthreads();
    for (int off = 128; off > 0; off >>= 1) {
        if (t < off) sh[t] += sh[t + off];
        __syncthreads();
    }
    if (t == 0) g_chunk[b] = sh[0];
}

__global__ void scan2_kernel(int nchunk) {
    __shared__ int sh[NCHUNK_MAX];
    int t = threadIdx.x;  // blockDim = 128
    int v = (t < nchunk) ? g_chunk[t] : 0;
    sh[t] = v;
    __syncthreads();
    for (int off = 1; off < NCHUNK_MAX; off <<= 1) {
        int add = (t >= off) ? sh[t - off] : 0;
        __syncthreads();
        sh[t] += add;
        __syncthreads();
    }
    if (t < nchunk) g_chunkbase[t] = sh[t] - v;  // exclusive base per chunk
}

__global__ void scan3_kernel(int n) {
    __shared__ int sh[256];
    int b = blockIdx.x, t = threadIdx.x;
    int base = b * 1024 + t * 4;
    int v[4];
#pragma unroll
    for (int j = 0; j < 4; j++) {
        int idx = base + j;
        v[j] = (idx < n) ? g_count[idx] : 0;
    }
    int tsum = v[0] + v[1] + v[2] + v[3];
    sh[t] = tsum;
    __syncthreads();
    for (int off = 1; off < 256; off <<= 1) {
        int add = (t >= off) ? sh[t - off] : 0;
        __syncthreads();
        sh[t] += add;
        __syncthreads();
    }
    int run = g_chunkbase[b] + (sh[t] - tsum);  // exclusive prefix
#pragma unroll
    for (int j = 0; j < 4; j++) {
        int idx = base + j;
        if (idx < n) g_offsets[idx] = run;
        run += v[j];
    }
}

__global__ void fill_kernel(const int* __restrict__ src,
                            const int* __restrict__ dst, int e) {
    int i = blockIdx.x * blockDim.x + threadIdx.x;
    if (i < e) {
        int d = dst[i];
        int pos = g_offsets[d] + atomicAdd(&g_cursor[d], 1);
        g_csr_src[pos] = src[i];
    }
}

// ---------------------------------------------------------------------------
// GEMM: C[n x 128] = A[n x 128] @ W[128 x 128]
// BM=64 rows per block, full W (64 KB) + padded x-tile (33 KB) in dyn smem.
// 256 threads, each computes a 4x8 micro-tile.
// ---------------------------------------------------------------------------
#define GEMM_BM 64
#define XS_STRIDE 129
#define GEMM_SMEM ((128 * 128 + GEMM_BM * XS_STRIDE) * (int)sizeof(float))

__global__ void __launch_bounds__(256, 2)
gemm_kernel(const float* __restrict__ A, const float* __restrict__ W,
            float* __restrict__ C, int n) {
    extern __shared__ float sm[];
    float* Ws = sm;                    // [128][128]
    float* Xs = sm + 128 * 128;        // [64][129]

    int tid = threadIdx.x;
    int tx = tid & 15;                 // col group: cols tx*8 .. tx*8+7
    int ty = tid >> 4;                 // row group: rows ty*4 .. ty*4+3
    int rowBase = blockIdx.x * GEMM_BM;

    // Load W (4096 float4, 16 per thread)
    const float4* W4 = (const float4*)W;
    float4* Ws4 = (float4*)Ws;
#pragma unroll
    for (int i = 0; i < 16; i++) Ws4[tid + i * 256] = W4[tid + i * 256];

    // Load X tile (2048 float4, 8 per thread), padded stride
    const float4* A4 = (const float4*)A;
#pragma unroll
    for (int i = 0; i < 8; i++) {
        int idx = tid + i * 256;       // 0..2047
        int r = idx >> 5;              // 0..63
        int c4 = idx & 31;
        float4 v = make_float4(0.f, 0.f, 0.f, 0.f);
        int grow = rowBase + r;
        if (grow < n) v = A4[(size_t)grow * 32 + c4];
        float* dstp = &Xs[r * XS_STRIDE + c4 * 4];
        dstp[0] = v.x; dstp[1] = v.y; dstp[2] = v.z; dstp[3] = v.w;
    }
    __syncthreads();

    float acc[4][8];
#pragma unroll
    for (int i = 0; i < 4; i++)
#pragma unroll
        for (int j = 0; j < 8; j++) acc[i][j] = 0.f;

#pragma unroll 8
    for (int k = 0; k < 128; k++) {
        float a0 = Xs[(ty * 4 + 0) * XS_STRIDE + k];
        float a1 = Xs[(ty * 4 + 1) * XS_STRIDE + k];
        float a2 = Xs[(ty * 4 + 2) * XS_STRIDE + k];
        float a3 = Xs[(ty * 4 + 3) * XS_STRIDE + k];
        float4 b0 = *(const float4*)&Ws[k * 128 + tx * 8];
        float4 b1 = *(const float4*)&Ws[k * 128 + tx * 8 + 4];
        float bb[8] = {b0.x, b0.y, b0.z, b0.w, b1.x, b1.y, b1.z, b1.w};
        float aa[4] = {a0, a1, a2, a3};
#pragma unroll
        for (int i = 0; i < 4; i++)
#pragma unroll
            for (int j = 0; j < 8; j++)
                acc[i][j] = fmaf(aa[i], bb[j], acc[i][j]);
    }

    float4* C4 = (float4*)C;
#pragma unroll
    for (int i = 0; i < 4; i++) {
        int grow = rowBase + ty * 4 + i;
        if (grow < n) {
            float4 o0 = make_float4(acc[i][0], acc[i][1], acc[i][2], acc[i][3]);
            float4 o1 = make_float4(acc[i][4], acc[i][5], acc[i][6], acc[i][7]);
            C4[(size_t)grow * 32 + tx * 2]     = o0;
            C4[(size_t)grow * 32 + tx * 2 + 1] = o1;
        }
    }
}

// ---------------------------------------------------------------------------
// Aggregation: warp per node.
// out[i] = relu( dis[i] * ( dis[i]*h[i] + sum_{e in csr(i)} dis[src]*h[src] ) + b )
// ---------------------------------------------------------------------------
__global__ void agg_kernel(const float* __restrict__ h, float* __restrict__ out,
                           const float* __restrict__ bias, int n) {
    int gw = (blockIdx.x * blockDim.x + threadIdx.x) >> 5;
    int lane = threadIdx.x & 31;
    if (gw >= n) return;

    int beg = g_offsets[gw];
    int end = g_offsets[gw + 1];
    float di = g_dis[gw];

    const float4* h4 = (const float4*)h;
    float4 hv = h4[(size_t)gw * 32 + lane];
    float4 acc;
    acc.x = di * hv.x; acc.y = di * hv.y; acc.z = di * hv.z; acc.w = di * hv.w;

    int e = beg;
    for (; e + 1 < end; e += 2) {
        int s0 = g_csr_src[e];
        int s1 = g_csr_src[e + 1];
        float w0 = g_dis[s0];
        float w1 = g_dis[s1];
        float4 v0 = h4[(size_t)s0 * 32 + lane];
        float4 v1 = h4[(size_t)s1 * 32 + lane];
        acc.x = fmaf(w0, v0.x, fmaf(w1, v1.x, acc.x));
        acc.y = fmaf(w0, v0.y, fmaf(w1, v1.y, acc.y));
        acc.z = fmaf(w0, v0.z, fmaf(w1, v1.z, acc.z));
        acc.w = fmaf(w0, v0.w, fmaf(w1, v1.w, acc.w));
    }
    if (e < end) {
        int s0 = g_csr_src[e];
        float w0 = g_dis[s0];
        float4 v0 = h4[(size_t)s0 * 32 + lane];
        acc.x = fmaf(w0, v0.x, acc.x);
        acc.y = fmaf(w0, v0.y, acc.y);
        acc.z = fmaf(w0, v0.z, acc.z);
        acc.w = fmaf(w0, v0.w, acc.w);
    }

    float4 bv = ((const float4*)bias)[lane];
    float4 r;
    r.x = fmaxf(fmaf(di, acc.x, bv.x), 0.f);
    r.y = fmaxf(fmaf(di, acc.y, bv.y), 0.f);
    r.z = fmaxf(fmaf(di, acc.z, bv.z), 0.f);
    r.w = fmaxf(fmaf(di, acc.w, bv.w), 0.f);
    ((float4*)out)[(size_t)gw * 32 + lane] = r;
}

// ---------------------------------------------------------------------------
// Layer 3: gemv (h @ W3 -> scalar per node), then scalar aggregation + sigmoid
// ---------------------------------------------------------------------------
__global__ void gemv_kernel(const float* __restrict__ h,
                            const float* __restrict__ W3,
                            float* __restrict__ g, int n) {
    int gw = (blockIdx.x * blockDim.x + threadIdx.x) >> 5;
    int lane = threadIdx.x & 31;
    if (gw >= n) return;
    float4 v = ((const float4*)h)[(size_t)gw * 32 + lane];
    float4 w = ((const float4*)W3)[lane];
    float p = v.x * w.x + v.y * w.y + v.z * w.z + v.w * w.w;
#pragma unroll
    for (int off = 16; off > 0; off >>= 1)
        p += __shfl_xor_sync(0xFFFFFFFFu, p, off);
    if (lane == 0) g[gw] = p;
}

__global__ void agg3_kernel(const float* __restrict__ g, float* __restrict__ out,
                            const float* __restrict__ b3, int n) {
    int i = blockIdx.x * blockDim.x + threadIdx.x;
    if (i >= n) return;
    int beg = g_offsets[i];
    int end = g_offsets[i + 1];
    float di = g_dis[i];
    float acc = di * g[i];
    for (int e = beg; e < end; e++) {
        int s = g_csr_src[e];
        acc = fmaf(g_dis[s], g[s], acc);
    }
    float z = fmaf(di, acc, b3[0]);
    out[i] = 1.0f / (1.0f + expf(-z));
}

// ---------------------------------------------------------------------------
// Launch
// ---------------------------------------------------------------------------
extern "C" void kernel_launch(void* const* d_in, const int* in_sizes, int n_in,
                              void* d_out, int out_size) {
    const float* x  = (const float*)d_in[0];
    const int*   ei = (const int*)d_in[1];
    const float* W1 = (const float*)d_in[2];
    const float* b1 = (const float*)d_in[3];
    const float* W2 = (const float*)d_in[4];
    const float* b2 = (const float*)d_in[5];
    const float* W3 = (const float*)d_in[6];
    const float* b3 = (const float*)d_in[7];
    float* out = (float*)d_out;

    int n = in_sizes[0] / F;          // 100000
    int e = in_sizes[1] / 2;          // 1600000
    const int* src = ei;
    const int* dst = ei + e;

    float *pA, *pB, *pS;
    cudaGetSymbolAddress((void**)&pA, g_bufA);
    cudaGetSymbolAddress((void**)&pB, g_bufB);
    cudaGetSymbolAddress((void**)&pS, g_scalar);

    cudaFuncSetAttribute(gemm_kernel,
                         cudaFuncAttributeMaxDynamicSharedMemorySize, GEMM_SMEM);

    int nchunk = (n + 1023) / 1024;

    // --- preprocessing: degrees, dis, CSR ---
    zero_kernel<<<(n + 255) / 256, 256>>>(n, e);
    count_kernel<<<(e + 255) / 256, 256>>>(dst, e);
    dis_kernel<<<(n + 255) / 256, 256>>>(n);
    scan1_kernel<<<nchunk, 256>>>(n);
    scan2_kernel<<<1, NCHUNK_MAX>>>(nchunk);
    scan3_kernel<<<nchunk, 256>>>(n);
    fill_kernel<<<(e + 255) / 256, 256>>>(src, dst, e);

    int gemm_grid = (n + GEMM_BM - 1) / GEMM_BM;
    int warp_grid = (n + 7) / 8;       // 8 warps / 256-thread block

    // --- layer 1 ---
    gemm_kernel<<<gemm_grid, 256, GEMM_SMEM>>>(x, W1, pA, n);
    agg_kernel<<<warp_grid, 256>>>(pA, pB, b1, n);
    // --- layer 2 ---
    gemm_kernel<<<gemm_grid, 256, GEMM_SMEM>>>(pB, W2, pA, n);
    agg_kernel<<<warp_grid, 256>>>(pA, pB, b2, n);
    // --- layer 3 ---
    gemv_kernel<<<warp_grid, 256>>>(pB, W3, pS, n);
    agg3_kernel<<<(n + 255) / 256, 256>>>(pS, out, b3, n);
}

// round 4
// speedup vs baseline: 1.0140x; 1.0140x over previous
#include <cuda_runtime.h>
#include <cuda_bf16.h>
#include <math.h>
#include <stdint.h>

// ---------------------------------------------------------------------------
// Problem constants
// ---------------------------------------------------------------------------
#define F 128
#define MAXN 102400
#define MAXE 1700000
#define NCHUNK_MAX 128

// ---------------------------------------------------------------------------
// Device scratch
// ---------------------------------------------------------------------------
__device__ float g_bufA[(size_t)MAXN * F];
__device__ float g_bufB[(size_t)MAXN * F];
__device__ float g_dis[MAXN];
__device__ float g_scalar[MAXN];
__device__ int   g_count[MAXN];
__device__ int   g_cursor[MAXN];
__device__ int   g_offsets[MAXN + 1];
__device__ int   g_csr_src[MAXE];
__device__ int   g_chunk[NCHUNK_MAX];
__device__ int   g_chunkbase[NCHUNK_MAX];

// ---------------------------------------------------------------------------
// Packed fp32x2 helpers (sm_100+): one instr = 2 fp32 FMAs
// ---------------------------------------------------------------------------
__device__ __forceinline__ uint64_t ffma2(uint64_t a, uint64_t b, uint64_t c) {
    uint64_t d;
    asm("fma.rn.f32x2 %0, %1, %2, %3;" : "=l"(d) : "l"(a), "l"(b), "l"(c));
    return d;
}
__device__ __forceinline__ uint64_t pack_dup(float a) {
    uint64_t r;
    asm("mov.b64 %0, {%1, %1};" : "=l"(r) : "f"(a));
    return r;
}
__device__ __forceinline__ void unpack2(uint64_t v, float& lo, float& hi) {
    asm("mov.b64 {%0, %1}, %2;" : "=f"(lo), "=f"(hi) : "l"(v));
}

// ---------------------------------------------------------------------------
// Preprocessing
// ---------------------------------------------------------------------------
__global__ void init_kernel(int n, int e) {
    if (blockIdx.x == 0 && threadIdx.x == 0) g_offsets[n] = e;
}

__global__ void count_kernel(const int* __restrict__ dst, int e) {
    int i = blockIdx.x * blockDim.x + threadIdx.x;
    if (i < e) atomicAdd(&g_count[dst[i]], 1);
}

__global__ void dis_kernel(int n) {
    int i = blockIdx.x * blockDim.x + threadIdx.x;
    if (i < n) g_dis[i] = rsqrtf((float)(g_count[i] + 1));
}

__global__ void scan1_kernel(int n) {
    __shared__ int sh[256];
    int b = blockIdx.x, t = threadIdx.x;
    int base = b * 1024 + t * 4;
    int s = 0;
#pragma unroll
    for (int j = 0; j < 4; j++) {
        int idx = base + j;
        if (idx < n) s += g_count[idx];
    }
    sh[t] = s;
    __syncthreads();
    for (int off = 128; off > 0; off >>= 1) {
        if (t < off) sh[t] += sh[t + off];
        __syncthreads();
    }
    if (t == 0) g_chunk[b] = sh[0];
}

__global__ void scan2_kernel(int nchunk) {
    __shared__ int sh[NCHUNK_MAX];
    int t = threadIdx.x;
    int v = (t < nchunk) ? g_chunk[t] : 0;
    sh[t] = v;
    __syncthreads();
    for (int off = 1; off < NCHUNK_MAX; off <<= 1) {
        int add = (t >= off) ? sh[t - off] : 0;
        __syncthreads();
        sh[t] += add;
        __syncthreads();
    }
    if (t < nchunk) g_chunkbase[t] = sh[t] - v;
}

__global__ void scan3_kernel(int n) {
    __shared__ int sh[256];
    int b = blockIdx.x, t = threadIdx.x;
    int base = b * 1024 + t * 4;
    int v[4];
#pragma unroll
    for (int j = 0; j < 4; j++) {
        int idx = base + j;
        v[j] = (idx < n) ? g_count[idx] : 0;
    }
    int tsum = v[0] + v[1] + v[2] + v[3];
    sh[t] = tsum;
    __syncthreads();
    for (int off = 1; off < 256; off <<= 1) {
        int add = (t >= off) ? sh[t - off] : 0;
        __syncthreads();
        sh[t] += add;
        __syncthreads();
    }
    int run = g_chunkbase[b] + (sh[t] - tsum);
#pragma unroll
    for (int j = 0; j < 4; j++) {
        int idx = base + j;
        if (idx < n) g_offsets[idx] = run;
        run += v[j];
    }
}

__global__ void fill_kernel(const int* __restrict__ src,
                            const int* __restrict__ dst, int e) {
    int i = blockIdx.x * blockDim.x + threadIdx.x;
    if (i < e) {
        int d = dst[i];
        int pos = g_offsets[d] + atomicAdd(&g_cursor[d], 1);
        g_csr_src[pos] = src[i];
    }
}

// ---------------------------------------------------------------------------
// GEMM: C[n x 128] = A[n x 128] @ W[128 x 128], packed f32x2 accumulators.
// 256 threads, 64 rows/block, each thread: 4 rows x 4 col-pairs (8 cols).
// ---------------------------------------------------------------------------
#define GEMM_BM 64
#define XS_STRIDE 129
#define GEMM_SMEM ((128 * 128 + GEMM_BM * XS_STRIDE) * (int)sizeof(float))

__global__ void __launch_bounds__(256, 1)
gemm_kernel(const float* __restrict__ A, const float* __restrict__ W,
            float* __restrict__ C, int n) {
    extern __shared__ float sm[];
    float* Ws = sm;                    // [128][128]
    float* Xs = sm + 128 * 128;        // [64][129]

    int tid = threadIdx.x;
    int tx = tid & 15;                 // cols tx*8 .. tx*8+7
    int ty = tid >> 4;                 // rows ty*4 .. ty*4+3
    int rowBase = blockIdx.x * GEMM_BM;

    // Load W (4096 float4, 16 per thread)
    const float4* W4 = (const float4*)W;
    float4* Ws4 = (float4*)Ws;
#pragma unroll
    for (int i = 0; i < 16; i++) Ws4[tid + i * 256] = W4[tid + i * 256];

    // Load X tile (2048 float4, 8 per thread), padded stride
    const float4* A4 = (const float4*)A;
#pragma unroll
    for (int i = 0; i < 8; i++) {
        int idx = tid + i * 256;
        int r = idx >> 5;
        int c4 = idx & 31;
        float4 v = make_float4(0.f, 0.f, 0.f, 0.f);
        int grow = rowBase + r;
        if (grow < n) v = A4[(size_t)grow * 32 + c4];
        float* dstp = &Xs[r * XS_STRIDE + c4 * 4];
        dstp[0] = v.x; dstp[1] = v.y; dstp[2] = v.z; dstp[3] = v.w;
    }
    __syncthreads();

    uint64_t acc[4][4];
#pragma unroll
    for (int i = 0; i < 4; i++)
#pragma unroll
        for (int j = 0; j < 4; j++) acc[i][j] = 0ull;

#pragma unroll 8
    for (int k = 0; k < 128; k++) {
        uint64_t pa[4];
#pragma unroll
        for (int i = 0; i < 4; i++)
            pa[i] = pack_dup(Xs[(ty * 4 + i) * XS_STRIDE + k]);

        ulonglong2 b0 = *(const ulonglong2*)&Ws[k * 128 + tx * 8];
        ulonglong2 b1 = *(const ulonglong2*)&Ws[k * 128 + tx * 8 + 4];
        uint64_t pb[4] = {b0.x, b0.y, b1.x, b1.y};

#pragma unroll
        for (int i = 0; i < 4; i++)
#pragma unroll
            for (int j = 0; j < 4; j++)
                acc[i][j] = ffma2(pa[i], pb[j], acc[i][j]);
    }

    float4* C4 = (float4*)C;
#pragma unroll
    for (int i = 0; i < 4; i++) {
        int grow = rowBase + ty * 4 + i;
        if (grow < n) {
            float4 o0, o1;
            unpack2(acc[i][0], o0.x, o0.y);
            unpack2(acc[i][1], o0.z, o0.w);
            unpack2(acc[i][2], o1.x, o1.y);
            unpack2(acc[i][3], o1.z, o1.w);
            C4[(size_t)grow * 32 + tx * 2]     = o0;
            C4[(size_t)grow * 32 + tx * 2 + 1] = o1;
        }
    }
}

// ---------------------------------------------------------------------------
// Aggregation: warp per node, 4-edge unroll for LDG MLP.
// ---------------------------------------------------------------------------
__global__ void agg_kernel(const float* __restrict__ h, float* __restrict__ out,
                           const float* __restrict__ bias, int n) {
    int gw = (blockIdx.x * blockDim.x + threadIdx.x) >> 5;
    int lane = threadIdx.x & 31;
    if (gw >= n) return;

    int beg = g_offsets[gw];
    int end = g_offsets[gw + 1];
    float di = g_dis[gw];

    const float4* h4 = (const float4*)h;
    float4 hv = h4[(size_t)gw * 32 + lane];
    float4 acc;
    acc.x = di * hv.x; acc.y = di * hv.y; acc.z = di * hv.z; acc.w = di * hv.w;

    int e = beg;
    for (; e + 3 < end; e += 4) {
        int s0 = g_csr_src[e];
        int s1 = g_csr_src[e + 1];
        int s2 = g_csr_src[e + 2];
        int s3 = g_csr_src[e + 3];
        float w0 = g_dis[s0];
        float w1 = g_dis[s1];
        float w2 = g_dis[s2];
        float w3 = g_dis[s3];
        float4 v0 = h4[(size_t)s0 * 32 + lane];
        float4 v1 = h4[(size_t)s1 * 32 + lane];
        float4 v2 = h4[(size_t)s2 * 32 + lane];
        float4 v3 = h4[(size_t)s3 * 32 + lane];
        acc.x = fmaf(w0, v0.x, acc.x); acc.y = fmaf(w0, v0.y, acc.y);
        acc.z = fmaf(w0, v0.z, acc.z); acc.w = fmaf(w0, v0.w, acc.w);
        acc.x = fmaf(w1, v1.x, acc.x); acc.y = fmaf(w1, v1.y, acc.y);
        acc.z = fmaf(w1, v1.z, acc.z); acc.w = fmaf(w1, v1.w, acc.w);
        acc.x = fmaf(w2, v2.x, acc.x); acc.y = fmaf(w2, v2.y, acc.y);
        acc.z = fmaf(w2, v2.z, acc.z); acc.w = fmaf(w2, v2.w, acc.w);
        acc.x = fmaf(w3, v3.x, acc.x); acc.y = fmaf(w3, v3.y, acc.y);
        acc.z = fmaf(w3, v3.z, acc.z); acc.w = fmaf(w3, v3.w, acc.w);
    }
    for (; e < end; e++) {
        int s0 = g_csr_src[e];
        float w0 = g_dis[s0];
        float4 v0 = h4[(size_t)s0 * 32 + lane];
        acc.x = fmaf(w0, v0.x, acc.x);
        acc.y = fmaf(w0, v0.y, acc.y);
        acc.z = fmaf(w0, v0.z, acc.z);
        acc.w = fmaf(w0, v0.w, acc.w);
    }

    float4 bv = ((const float4*)bias)[lane];
    float4 r;
    r.x = fmaxf(fmaf(di, acc.x, bv.x), 0.f);
    r.y = fmaxf(fmaf(di, acc.y, bv.y), 0.f);
    r.z = fmaxf(fmaf(di, acc.z, bv.z), 0.f);
    r.w = fmaxf(fmaf(di, acc.w, bv.w), 0.f);
    ((float4*)out)[(size_t)gw * 32 + lane] = r;
}

// ---------------------------------------------------------------------------
// Layer 3
// ---------------------------------------------------------------------------
__global__ void gemv_kernel(const float* __restrict__ h,
                            const float* __restrict__ W3,
                            float* __restrict__ g, int n) {
    int gw = (blockIdx.x * blockDim.x + threadIdx.x) >> 5;
    int lane = threadIdx.x & 31;
    if (gw >= n) return;
    float4 v = ((const float4*)h)[(size_t)gw * 32 + lane];
    float4 w = ((const float4*)W3)[lane];
    float p = v.x * w.x + v.y * w.y + v.z * w.z + v.w * w.w;
#pragma unroll
    for (int off = 16; off > 0; off >>= 1)
        p += __shfl_xor_sync(0xFFFFFFFFu, p, off);
    if (lane == 0) g[gw] = p;
}

__global__ void agg3_kernel(const float* __restrict__ g, float* __restrict__ out,
                            const float* __restrict__ b3, int n) {
    int i = blockIdx.x * blockDim.x + threadIdx.x;
    if (i >= n) return;
    int beg = g_offsets[i];
    int end = g_offsets[i + 1];
    float di = g_dis[i];
    float acc = di * g[i];
    for (int e = beg; e < end; e++) {
        int s = g_csr_src[e];
        acc = fmaf(g_dis[s], g[s], acc);
    }
    float z = fmaf(di, acc, b3[0]);
    out[i] = 1.0f / (1.0f + expf(-z));
}

// ---------------------------------------------------------------------------
// Launch
// ---------------------------------------------------------------------------
extern "C" void kernel_launch(void* const* d_in, const int* in_sizes, int n_in,
                              void* d_out, int out_size) {
    const float* x  = (const float*)d_in[0];
    const int*   ei = (const int*)d_in[1];
    const float* W1 = (const float*)d_in[2];
    const float* b1 = (const float*)d_in[3];
    const float* W2 = (const float*)d_in[4];
    const float* b2 = (const float*)d_in[5];
    const float* W3 = (const float*)d_in[6];
    const float* b3 = (const float*)d_in[7];
    float* out = (float*)d_out;

    int n = in_sizes[0] / F;          // 100000
    int e = in_sizes[1] / 2;          // 1600000
    const int* src = ei;
    const int* dst = ei + e;

    float *pA, *pB, *pS;
    int *pCount, *pCursor;
    cudaGetSymbolAddress((void**)&pA, g_bufA);
    cudaGetSymbolAddress((void**)&pB, g_bufB);
    cudaGetSymbolAddress((void**)&pS, g_scalar);
    cudaGetSymbolAddress((void**)&pCount, g_count);
    cudaGetSymbolAddress((void**)&pCursor, g_cursor);

    cudaFuncSetAttribute(gemm_kernel,
                         cudaFuncAttributeMaxDynamicSharedMemorySize, GEMM_SMEM);

    int nchunk = (n + 1023) / 1024;

    // --- preprocessing: degrees, dis, CSR ---
    cudaMemsetAsync(pCount, 0, n * sizeof(int));
    cudaMemsetAsync(pCursor, 0, n * sizeof(int));
    init_kernel<<<1, 32>>>(n, e);
    count_kernel<<<(e + 255) / 256, 256>>>(dst, e);
    dis_kernel<<<(n + 255) / 256, 256>>>(n);
    scan1_kernel<<<nchunk, 256>>>(n);
    scan2_kernel<<<1, NCHUNK_MAX>>>(nchunk);
    scan3_kernel<<<nchunk, 256>>>(n);
    fill_kernel<<<(e + 255) / 256, 256>>>(src, dst, e);

    int gemm_grid = (n + GEMM_BM - 1) / GEMM_BM;
    int warp_grid = (n + 7) / 8;

    // --- layer 1 ---
    gemm_kernel<<<gemm_grid, 256, GEMM_SMEM>>>(x, W1, pA, n);
    agg_kernel<<<warp_grid, 256>>>(pA, pB, b1, n);
    // --- layer 2 ---
    gemm_kernel<<<gemm_grid, 256, GEMM_SMEM>>>(pB, W2, pA, n);
    agg_kernel<<<warp_grid, 256>>>(pA, pB, b2, n);
    // --- layer 3 ---
    gemv_kernel<<<warp_grid, 256>>>(pB, W3, pS, n);
    agg3_kernel<<<(n + 255) / 256, 256>>>(pS, out, b3, n);
}

// round 5
// speedup vs baseline: 1.0470x; 1.0326x over previous
#include <cuda_runtime.h>
#include <cuda_bf16.h>
#include <math.h>
#include <stdint.h>

// ---------------------------------------------------------------------------
// Problem constants
// ---------------------------------------------------------------------------
#define F 128
#define MAXN 102400
#define MAXE 1700000
#define NCHUNK_MAX 128

// ---------------------------------------------------------------------------
// Device scratch
// ---------------------------------------------------------------------------
__device__ float g_bufA[(size_t)MAXN * F];
__device__ float g_bufB[(size_t)MAXN * F];
__device__ float g_dis[MAXN];
__device__ float g_scalar[MAXN];
__device__ int   g_count[MAXN];
__device__ int   g_cursor[MAXN];
__device__ int   g_offsets[MAXN + 1];
__device__ int   g_csr_src[MAXE];
__device__ int   g_chunk[NCHUNK_MAX];
__device__ int   g_chunkbase[NCHUNK_MAX];

// ---------------------------------------------------------------------------
// Packed fp32x2 helpers (sm_100+)
// ---------------------------------------------------------------------------
__device__ __forceinline__ uint64_t ffma2(uint64_t a, uint64_t b, uint64_t c) {
    uint64_t d;
    asm("fma.rn.f32x2 %0, %1, %2, %3;" : "=l"(d) : "l"(a), "l"(b), "l"(c));
    return d;
}
__device__ __forceinline__ uint64_t pack_dup(float a) {
    uint64_t r;
    asm("mov.b64 %0, {%1, %1};" : "=l"(r) : "f"(a));
    return r;
}
__device__ __forceinline__ void unpack2(uint64_t v, float& lo, float& hi) {
    asm("mov.b64 {%0, %1}, %2;" : "=f"(lo), "=f"(hi) : "l"(v));
}

// ---------------------------------------------------------------------------
// Preprocessing
// ---------------------------------------------------------------------------
__global__ void init_kernel(int n, int e) {
    if (blockIdx.x == 0 && threadIdx.x == 0) g_offsets[n] = e;
}

__global__ void count_kernel(const int* __restrict__ dst, int e) {
    int i = blockIdx.x * blockDim.x + threadIdx.x;
    if (i < e) atomicAdd(&g_count[dst[i]], 1);
}

__global__ void dis_kernel(int n) {
    int i = blockIdx.x * blockDim.x + threadIdx.x;
    if (i < n) g_dis[i] = rsqrtf((float)(g_count[i] + 1));
}

__global__ void scan1_kernel(int n) {
    __shared__ int sh[256];
    int b = blockIdx.x, t = threadIdx.x;
    int base = b * 1024 + t * 4;
    int s = 0;
#pragma unroll
    for (int j = 0; j < 4; j++) {
        int idx = base + j;
        if (idx < n) s += g_count[idx];
    }
    sh[t] = s;
    __syncthreads();
    for (int off = 128; off > 0; off >>= 1) {
        if (t < off) sh[t] += sh[t + off];
        __syncthreads();
    }
    if (t == 0) g_chunk[b] = sh[0];
}

__global__ void scan2_kernel(int nchunk) {
    __shared__ int sh[NCHUNK_MAX];
    int t = threadIdx.x;
    int v = (t < nchunk) ? g_chunk[t] : 0;
    sh[t] = v;
    __syncthreads();
    for (int off = 1; off < NCHUNK_MAX; off <<= 1) {
        int add = (t >= off) ? sh[t - off] : 0;
        __syncthreads();
        sh[t] += add;
        __syncthreads();
    }
    if (t < nchunk) g_chunkbase[t] = sh[t] - v;
}

__global__ void scan3_kernel(int n) {
    __shared__ int sh[256];
    int b = blockIdx.x, t = threadIdx.x;
    int base = b * 1024 + t * 4;
    int v[4];
#pragma unroll
    for (int j = 0; j < 4; j++) {
        int idx = base + j;
        v[j] = (idx < n) ? g_count[idx] : 0;
    }
    int tsum = v[0] + v[1] + v[2] + v[3];
    sh[t] = tsum;
    __syncthreads();
    for (int off = 1; off < 256; off <<= 1) {
        int add = (t >= off) ? sh[t - off] : 0;
        __syncthreads();
        sh[t] += add;
        __syncthreads();
    }
    int run = g_chunkbase[b] + (sh[t] - tsum);
#pragma unroll
    for (int j = 0; j < 4; j++) {
        int idx = base + j;
        if (idx < n) g_offsets[idx] = run;
        run += v[j];
    }
}

__global__ void fill_kernel(const int* __restrict__ src,
                            const int* __restrict__ dst, int e) {
    int i = blockIdx.x * blockDim.x + threadIdx.x;
    if (i < e) {
        int d = dst[i];
        int pos = g_offsets[d] + atomicAdd(&g_cursor[d], 1);
        g_csr_src[pos] = src[i];
    }
}

// ---------------------------------------------------------------------------
// GEMM: C[n x 128] = scale[row] * (A[n x 128] @ W[128 x 128])
// Pre-scaled output h' = dis*h so the aggregation needs no per-edge weight.
// ---------------------------------------------------------------------------
#define GEMM_BM 64
#define XS_STRIDE 129
#define GEMM_SMEM ((128 * 128 + GEMM_BM * XS_STRIDE) * (int)sizeof(float))

__global__ void __launch_bounds__(256, 1)
gemm_kernel(const float* __restrict__ A, const float* __restrict__ W,
            float* __restrict__ C, const float* __restrict__ scale, int n) {
    extern __shared__ float sm[];
    float* Ws = sm;                    // [128][128]
    float* Xs = sm + 128 * 128;        // [64][129]

    int tid = threadIdx.x;
    int tx = tid & 15;
    int ty = tid >> 4;
    int rowBase = blockIdx.x * GEMM_BM;

    const float4* W4 = (const float4*)W;
    float4* Ws4 = (float4*)Ws;
#pragma unroll
    for (int i = 0; i < 16; i++) Ws4[tid + i * 256] = W4[tid + i * 256];

    const float4* A4 = (const float4*)A;
#pragma unroll
    for (int i = 0; i < 8; i++) {
        int idx = tid + i * 256;
        int r = idx >> 5;
        int c4 = idx & 31;
        float4 v = make_float4(0.f, 0.f, 0.f, 0.f);
        int grow = rowBase + r;
        if (grow < n) v = A4[(size_t)grow * 32 + c4];
        float* dstp = &Xs[r * XS_STRIDE + c4 * 4];
        dstp[0] = v.x; dstp[1] = v.y; dstp[2] = v.z; dstp[3] = v.w;
    }
    __syncthreads();

    uint64_t acc[4][4];
#pragma unroll
    for (int i = 0; i < 4; i++)
#pragma unroll
        for (int j = 0; j < 4; j++) acc[i][j] = 0ull;

#pragma unroll 8
    for (int k = 0; k < 128; k++) {
        uint64_t pa[4];
#pragma unroll
        for (int i = 0; i < 4; i++)
            pa[i] = pack_dup(Xs[(ty * 4 + i) * XS_STRIDE + k]);

        ulonglong2 b0 = *(const ulonglong2*)&Ws[k * 128 + tx * 8];
        ulonglong2 b1 = *(const ulonglong2*)&Ws[k * 128 + tx * 8 + 4];
        uint64_t pb[4] = {b0.x, b0.y, b1.x, b1.y};

#pragma unroll
        for (int i = 0; i < 4; i++)
#pragma unroll
            for (int j = 0; j < 4; j++)
                acc[i][j] = ffma2(pa[i], pb[j], acc[i][j]);
    }

    float4* C4 = (float4*)C;
#pragma unroll
    for (int i = 0; i < 4; i++) {
        int grow = rowBase + ty * 4 + i;
        if (grow < n) {
            float s = scale[grow];
            float4 o0, o1;
            unpack2(acc[i][0], o0.x, o0.y);
            unpack2(acc[i][1], o0.z, o0.w);
            unpack2(acc[i][2], o1.x, o1.y);
            unpack2(acc[i][3], o1.z, o1.w);
            o0.x *= s; o0.y *= s; o0.z *= s; o0.w *= s;
            o1.x *= s; o1.y *= s; o1.z *= s; o1.w *= s;
            C4[(size_t)grow * 32 + tx * 2]     = o0;
            C4[(size_t)grow * 32 + tx * 2 + 1] = o1;
        }
    }
}

// ---------------------------------------------------------------------------
// Aggregation: warp per node. Input rows are pre-scaled (h' = dis*h), so the
// inner loop is a pure gather-accumulate: no per-edge weight load.
// out[i] = relu( dis[i] * ( h'[i] + sum_e h'[src_e] ) + b )
// ---------------------------------------------------------------------------
__global__ void agg_kernel(const float* __restrict__ h, float* __restrict__ out,
                           const float* __restrict__ bias, int n) {
    int gw = (blockIdx.x * blockDim.x + threadIdx.x) >> 5;
    int lane = threadIdx.x & 31;
    if (gw >= n) return;

    int beg = g_offsets[gw];
    int end = g_offsets[gw + 1];
    float di = g_dis[gw];

    const float4* h4 = (const float4*)h;
    float4 acc = h4[(size_t)gw * 32 + lane];   // self-loop term (pre-scaled)

    int e = beg;
    for (; e + 3 < end; e += 4) {
        int s0 = g_csr_src[e];
        int s1 = g_csr_src[e + 1];
        int s2 = g_csr_src[e + 2];
        int s3 = g_csr_src[e + 3];
        float4 v0 = h4[(size_t)s0 * 32 + lane];
        float4 v1 = h4[(size_t)s1 * 32 + lane];
        float4 v2 = h4[(size_t)s2 * 32 + lane];
        float4 v3 = h4[(size_t)s3 * 32 + lane];
        acc.x += v0.x + v1.x + v2.x + v3.x;
        acc.y += v0.y + v1.y + v2.y + v3.y;
        acc.z += v0.z + v1.z + v2.z + v3.z;
        acc.w += v0.w + v1.w + v2.w + v3.w;
    }
    for (; e < end; e++) {
        int s0 = g_csr_src[e];
        float4 v0 = h4[(size_t)s0 * 32 + lane];
        acc.x += v0.x; acc.y += v0.y; acc.z += v0.z; acc.w += v0.w;
    }

    float4 bv = ((const float4*)bias)[lane];
    float4 r;
    r.x = fmaxf(fmaf(di, acc.x, bv.x), 0.f);
    r.y = fmaxf(fmaf(di, acc.y, bv.y), 0.f);
    r.z = fmaxf(fmaf(di, acc.z, bv.z), 0.f);
    r.w = fmaxf(fmaf(di, acc.w, bv.w), 0.f);
    ((float4*)out)[(size_t)gw * 32 + lane] = r;
}

// ---------------------------------------------------------------------------
// Layer 3: gemv with fused dis-scaling (g'[i] = dis[i] * h[i]·W3)
// ---------------------------------------------------------------------------
__global__ void gemv_kernel(const float* __restrict__ h,
                            const float* __restrict__ W3,
                            float* __restrict__ g, int n) {
    int gw = (blockIdx.x * blockDim.x + threadIdx.x) >> 5;
    int lane = threadIdx.x & 31;
    if (gw >= n) return;
    float4 v = ((const float4*)h)[(size_t)gw * 32 + lane];
    float4 w = ((const float4*)W3)[lane];
    float p = v.x * w.x + v.y * w.y + v.z * w.z + v.w * w.w;
#pragma unroll
    for (int off = 16; off > 0; off >>= 1)
        p += __shfl_xor_sync(0xFFFFFFFFu, p, off);
    if (lane == 0) g[gw] = g_dis[gw] * p;
}

__global__ void agg3_kernel(const float* __restrict__ g, float* __restrict__ out,
                            const float* __restrict__ b3, int n) {
    int i = blockIdx.x * blockDim.x + threadIdx.x;
    if (i >= n) return;
    int beg = g_offsets[i];
    int end = g_offsets[i + 1];
    float di = g_dis[i];
    float acc = g[i];                  // self-loop (pre-scaled)
    for (int e = beg; e < end; e++) {
        acc += g[g_csr_src[e]];
    }
    float z = fmaf(di, acc, b3[0]);
    out[i] = 1.0f / (1.0f + expf(-z));
}

// ---------------------------------------------------------------------------
// Launch.  Node order matters for ncu (-s 5 -c 1 captures graph node #6):
//   1 memset, 2 memset, 3 init, 4 count, 5 dis, 6 gemm1  <-- profiled
// gemm1 is legal there: it needs only x, W1, dis.
// ---------------------------------------------------------------------------
extern "C" void kernel_launch(void* const* d_in, const int* in_sizes, int n_in,
                              void* d_out, int out_size) {
    const float* x  = (const float*)d_in[0];
    const int*   ei = (const int*)d_in[1];
    const float* W1 = (const float*)d_in[2];
    const float* b1 = (const float*)d_in[3];
    const float* W2 = (const float*)d_in[4];
    const float* b2 = (const float*)d_in[5];
    const float* W3 = (const float*)d_in[6];
    const float* b3 = (const float*)d_in[7];
    float* out = (float*)d_out;

    int n = in_sizes[0] / F;          // 100000
    int e = in_sizes[1] / 2;          // 1600000
    const int* src = ei;
    const int* dst = ei + e;

    float *pA, *pB, *pS, *pDis;
    int *pCount, *pCursor;
    cudaGetSymbolAddress((void**)&pA, g_bufA);
    cudaGetSymbolAddress((void**)&pB, g_bufB);
    cudaGetSymbolAddress((void**)&pS, g_scalar);
    cudaGetSymbolAddress((void**)&pDis, g_dis);
    cudaGetSymbolAddress((void**)&pCount, g_count);
    cudaGetSymbolAddress((void**)&pCursor, g_cursor);

    cudaFuncSetAttribute(gemm_kernel,
                         cudaFuncAttributeMaxDynamicSharedMemorySize, GEMM_SMEM);

    int nchunk = (n + 1023) / 1024;
    int gemm_grid = (n + GEMM_BM - 1) / GEMM_BM;
    int warp_grid = (n + 7) / 8;

    // nodes 1-5
    cudaMemsetAsync(pCount, 0, n * sizeof(int));
    cudaMemsetAsync(pCursor, 0, n * sizeof(int));
    init_kernel<<<1, 32>>>(n, e);
    count_kernel<<<(e + 255) / 256, 256>>>(dst, e);
    dis_kernel<<<(n + 255) / 256, 256>>>(n);

    // node 6: layer-1 GEMM (profiled by ncu -s 5 -c 1)
    gemm_kernel<<<gemm_grid, 256, GEMM_SMEM>>>(x, W1, pA, pDis, n);

    // CSR build
    scan1_kernel<<<nchunk, 256>>>(n);
    scan2_kernel<<<1, NCHUNK_MAX>>>(nchunk);
    scan3_kernel<<<nchunk, 256>>>(n);
    fill_kernel<<<(e + 255) / 256, 256>>>(src, dst, e);

    // layer 1 aggregation
    agg_kernel<<<warp_grid, 256>>>(pA, pB, b1, n);
    // layer 2
    gemm_kernel<<<gemm_grid, 256, GEMM_SMEM>>>(pB, W2, pA, pDis, n);
    agg_kernel<<<warp_grid, 256>>>(pA, pB, b2, n);
    // layer 3
    gemv_kernel<<<warp_grid, 256>>>(pB, W3, pS, n);
    agg3_kernel<<<(n + 255) / 256, 256>>>(pS, out, b3, n);
}

// round 7
// speedup vs baseline: 1.0656x; 1.0178x over previous
#include <cuda_runtime.h>
#include <cuda_bf16.h>
#include <math.h>
#include <stdint.h>

// ---------------------------------------------------------------------------
// Problem constants
// ---------------------------------------------------------------------------
#define F 128
#define MAXN 102400
#define MAXE 1700000
#define NCHUNK_MAX 128

// ---------------------------------------------------------------------------
// Device scratch
// ---------------------------------------------------------------------------
__device__ float g_bufA[(size_t)MAXN * F];
__device__ float g_bufB[(size_t)MAXN * F];
__device__ float g_dis[MAXN];
__device__ float g_scalar[MAXN];
__device__ int   g_count[MAXN];
__device__ int   g_cursor[MAXN];
__device__ int   g_offsets[MAXN + 1];
__device__ int   g_csr_src[MAXE];
__device__ int   g_chunk[NCHUNK_MAX];
__device__ int   g_chunkbase[NCHUNK_MAX];

// ---------------------------------------------------------------------------
// Packed fp32x2 helpers (sm_100+)
// ---------------------------------------------------------------------------
__device__ __forceinline__ uint64_t ffma2(uint64_t a, uint64_t b, uint64_t c) {
    uint64_t d;
    asm("fma.rn.f32x2 %0, %1, %2, %3;" : "=l"(d) : "l"(a), "l"(b), "l"(c));
    return d;
}
__device__ __forceinline__ uint64_t pack_dup(float a) {
    uint64_t r;
    asm("mov.b64 %0, {%1, %1};" : "=l"(r) : "f"(a));
    return r;
}
__device__ __forceinline__ void unpack2(uint64_t v, float& lo, float& hi) {
    asm("mov.b64 {%0, %1}, %2;" : "=f"(lo), "=f"(hi) : "l"(v));
}

// ---------------------------------------------------------------------------
// Preprocessing
// ---------------------------------------------------------------------------
__global__ void init_kernel(int n, int e) {
    if (blockIdx.x == 0 && threadIdx.x == 0) g_offsets[n] = e;
}

__global__ void count_kernel(const int* __restrict__ dst, int e) {
    int i = blockIdx.x * blockDim.x + threadIdx.x;
    if (i < e) atomicAdd(&g_count[dst[i]], 1);
}

__global__ void dis_kernel(int n) {
    int i = blockIdx.x * blockDim.x + threadIdx.x;
    if (i < n) g_dis[i] = rsqrtf((float)(g_count[i] + 1));
}

__global__ void scan1_kernel(int n) {
    __shared__ int sh[256];
    int b = blockIdx.x, t = threadIdx.x;
    int base = b * 1024 + t * 4;
    int s = 0;
#pragma unroll
    for (int j = 0; j < 4; j++) {
        int idx = base + j;
        if (idx < n) s += g_count[idx];
    }
    sh[t] = s;
    __syncthreads();
    for (int off = 128; off > 0; off >>= 1) {
        if (t < off) sh[t] += sh[t + off];
        __syncthreads();
    }
    if (t == 0) g_chunk[b] = sh[0];
}

__global__ void scan2_kernel(int nchunk) {
    __shared__ int sh[NCHUNK_MAX];
    int t = threadIdx.x;
    int v = (t < nchunk) ? g_chunk[t] : 0;
    sh[t] = v;
    __syncthreads();
    for (int off = 1; off < NCHUNK_MAX; off <<= 1) {
        int add = (t >= off) ? sh[t - off] : 0;
        __syncthreads();
        sh[t] += add;
        __syncthreads();
    }
    if (t < nchunk) g_chunkbase[t] = sh[t] - v;
}

__global__ void scan3_kernel(int n) {
    __shared__ int sh[256];
    int b = blockIdx.x, t = threadIdx.x;
    int base = b * 1024 + t * 4;
    int v[4];
#pragma unroll
    for (int j = 0; j < 4; j++) {
        int idx = base + j;
        v[j] = (idx < n) ? g_count[idx] : 0;
    }
    int tsum = v[0] + v[1] + v[2] + v[3];
    sh[t] = tsum;
    __syncthreads();
    for (int off = 1; off < 256; off <<= 1) {
        int add = (t >= off) ? sh[t - off] : 0;
        __syncthreads();
        sh[t] += add;
        __syncthreads();
    }
    int run = g_chunkbase[b] + (sh[t] - tsum);
#pragma unroll
    for (int j = 0; j < 4; j++) {
        int idx = base + j;
        if (idx < n) g_offsets[idx] = run;
        run += v[j];
    }
}

__global__ void fill_kernel(const int* __restrict__ src,
                            const int* __restrict__ dst, int e) {
    int i = blockIdx.x * blockDim.x + threadIdx.x;
    if (i < e) {
        int d = dst[i];
        int pos = g_offsets[d] + atomicAdd(&g_cursor[d], 1);
        g_csr_src[pos] = src[i];
    }
}

// ---------------------------------------------------------------------------
// GEMM: C[n x 128] = scale[row] * (A[n x 128] @ W[128 x 128])
// f32x2 packed accumulators; Xs read as float4 over k to cut LDS wavefronts.
// ---------------------------------------------------------------------------
#define GEMM_BM 64
#define XS_STRIDE 132            // multiple of 4 -> float4-aligned rows
#define GEMM_SMEM ((128 * 128 + GEMM_BM * XS_STRIDE) * (int)sizeof(float))

__global__ void __launch_bounds__(256, 2)
gemm_kernel(const float* __restrict__ A, const float* __restrict__ W,
            float* __restrict__ C, const float* __restrict__ scale, int n) {
    extern __shared__ float sm[];
    float* Ws = sm;                    // [128][128]
    float* Xs = sm + 128 * 128;        // [64][132]

    int tid = threadIdx.x;
    int tx = tid & 15;                 // cols tx*8 .. tx*8+7
    int ty = tid >> 4;                 // rows ty*4 .. ty*4+3
    int rowBase = blockIdx.x * GEMM_BM;

    // Load W (4096 float4, 16 per thread)
    const float4* W4 = (const float4*)W;
    float4* Ws4 = (float4*)Ws;
#pragma unroll
    for (int i = 0; i < 16; i++) Ws4[tid + i * 256] = W4[tid + i * 256];

    // Load X tile (2048 float4, 8 per thread), padded stride (16B aligned rows)
    const float4* A4 = (const float4*)A;
#pragma unroll
    for (int i = 0; i < 8; i++) {
        int idx = tid + i * 256;
        int r = idx >> 5;
        int c4 = idx & 31;
        float4 v = make_float4(0.f, 0.f, 0.f, 0.f);
        int grow = rowBase + r;
        if (grow < n) v = A4[(size_t)grow * 32 + c4];
        *(float4*)&Xs[r * XS_STRIDE + c4 * 4] = v;
    }
    __syncthreads();

    uint64_t acc[4][4];
#pragma unroll
    for (int i = 0; i < 4; i++)
#pragma unroll
        for (int j = 0; j < 4; j++) acc[i][j] = 0ull;

#pragma unroll 2
    for (int k4 = 0; k4 < 32; k4++) {
        // One LDS.128 per row covers 4 k-values (broadcast across tx).
        float av[4][4];
#pragma unroll
        for (int i = 0; i < 4; i++)
            *(float4*)av[i] = *(const float4*)&Xs[(ty * 4 + i) * XS_STRIDE + k4 * 4];

#pragma unroll
        for (int kk = 0; kk < 4; kk++) {
            int k = k4 * 4 + kk;
            ulonglong2 b0 = *(const ulonglong2*)&Ws[k * 128 + tx * 8];
            ulonglong2 b1 = *(const ulonglong2*)&Ws[k * 128 + tx * 8 + 4];
            uint64_t pb[4] = {b0.x, b0.y, b1.x, b1.y};
            uint64_t pa[4];
#pragma unroll
            for (int i = 0; i < 4; i++) pa[i] = pack_dup(av[i][kk]);
#pragma unroll
            for (int i = 0; i < 4; i++)
#pragma unroll
                for (int j = 0; j < 4; j++)
                    acc[i][j] = ffma2(pa[i], pb[j], acc[i][j]);
        }
    }

    float4* C4 = (float4*)C;
#pragma unroll
    for (int i = 0; i < 4; i++) {
        int grow = rowBase + ty * 4 + i;
        if (grow < n) {
            float s = scale[grow];
            float4 o0, o1;
            unpack2(acc[i][0], o0.x, o0.y);
            unpack2(acc[i][1], o0.z, o0.w);
            unpack2(acc[i][2], o1.x, o1.y);
            unpack2(acc[i][3], o1.z, o1.w);
            o0.x *= s; o0.y *= s; o0.z *= s; o0.w *= s;
            o1.x *= s; o1.y *= s; o1.z *= s; o1.w *= s;
            C4[(size_t)grow * 32 + tx * 2]     = o0;
            C4[(size_t)grow * 32 + tx * 2 + 1] = o1;
        }
    }
}

// ---------------------------------------------------------------------------
// Aggregation: warp per node, pure gather-accumulate (rows pre-scaled).
// out[i] = relu( dis[i] * ( h'[i] + sum_e h'[src_e] ) + b )
// ---------------------------------------------------------------------------
__global__ void agg_kernel(const float* __restrict__ h, float* __restrict__ out,
                           const float* __restrict__ bias, int n) {
    int gw = (blockIdx.x * blockDim.x + threadIdx.x) >> 5;
    int lane = threadIdx.x & 31;
    if (gw >= n) return;

    int beg = g_offsets[gw];
    int end = g_offsets[gw + 1];
    float di = g_dis[gw];

    const float4* h4 = (const float4*)h;
    float4 acc = h4[(size_t)gw * 32 + lane];

    int e = beg;
    for (; e + 3 < end; e += 4) {
        int s0 = g_csr_src[e];
        int s1 = g_csr_src[e + 1];
        int s2 = g_csr_src[e + 2];
        int s3 = g_csr_src[e + 3];
        float4 v0 = h4[(size_t)s0 * 32 + lane];
        float4 v1 = h4[(size_t)s1 * 32 + lane];
        float4 v2 = h4[(size_t)s2 * 32 + lane];
        float4 v3 = h4[(size_t)s3 * 32 + lane];
        acc.x += v0.x + v1.x + v2.x + v3.x;
        acc.y += v0.y + v1.y + v2.y + v3.y;
        acc.z += v0.z + v1.z + v2.z + v3.z;
        acc.w += v0.w + v1.w + v2.w + v3.w;
    }
    for (; e < end; e++) {
        int s0 = g_csr_src[e];
        float4 v0 = h4[(size_t)s0 * 32 + lane];
        acc.x += v0.x; acc.y += v0.y; acc.z += v0.z; acc.w += v0.w;
    }

    float4 bv = ((const float4*)bias)[lane];
    float4 r;
    r.x = fmaxf(fmaf(di, acc.x, bv.x), 0.f);
    r.y = fmaxf(fmaf(di, acc.y, bv.y), 0.f);
    r.z = fmaxf(fmaf(di, acc.z, bv.z), 0.f);
    r.w = fmaxf(fmaf(di, acc.w, bv.w), 0.f);
    ((float4*)out)[(size_t)gw * 32 + lane] = r;
}

// ---------------------------------------------------------------------------
// Layer 3
// ---------------------------------------------------------------------------
__global__ void gemv_kernel(const float* __restrict__ h,
                            const float* __restrict__ W3,
                            float* __restrict__ g, int n) {
    int gw = (blockIdx.x * blockDim.x + threadIdx.x) >> 5;
    int lane = threadIdx.x & 31;
    if (gw >= n) return;
    float4 v = ((const float4*)h)[(size_t)gw * 32 + lane];
    float4 w = ((const float4*)W3)[lane];
    float p = v.x * w.x + v.y * w.y + v.z * w.z + v.w * w.w;
#pragma unroll
    for (int off = 16; off > 0; off >>= 1)
        p += __shfl_xor_sync(0xFFFFFFFFu, p, off);
    if (lane == 0) g[gw] = g_dis[gw] * p;
}

__global__ void agg3_kernel(const float* __restrict__ g, float* __restrict__ out,
                            const float* __restrict__ b3, int n) {
    int i = blockIdx.x * blockDim.x + threadIdx.x;
    if (i >= n) return;
    int beg = g_offsets[i];
    int end = g_offsets[i + 1];
    float di = g_dis[i];
    float acc = g[i];
    for (int e = beg; e < end; e++) {
        acc += g[g_csr_src[e]];
    }
    float z = fmaf(di, acc, b3[0]);
    out[i] = 1.0f / (1.0f + expf(-z));
}

// ---------------------------------------------------------------------------
// Launch.  Node order keeps gemm1 at graph node #6 so ncu -s 5 -c 1 profiles it.
// ---------------------------------------------------------------------------
extern "C" void kernel_launch(void* const* d_in, const int* in_sizes, int n_in,
                              void* d_out, int out_size) {
    const float* x  = (const float*)d_in[0];
    const int*   ei = (const int*)d_in[1];
    const float* W1 = (const float*)d_in[2];
    const float* b1 = (const float*)d_in[3];
    const float* W2 = (const float*)d_in[4];
    const float* b2 = (const float*)d_in[5];
    const float* W3 = (const float*)d_in[6];
    const float* b3 = (const float*)d_in[7];
    float* out = (float*)d_out;

    int n = in_sizes[0] / F;          // 100000
    int e = in_sizes[1] / 2;          // 1600000
    const int* src = ei;
    const int* dst = ei + e;

    float *pA, *pB, *pS, *pDis;
    int *pCount, *pCursor;
    cudaGetSymbolAddress((void**)&pA, g_bufA);
    cudaGetSymbolAddress((void**)&pB, g_bufB);
    cudaGetSymbolAddress((void**)&pS, g_scalar);
    cudaGetSymbolAddress((void**)&pDis, g_dis);
    cudaGetSymbolAddress((void**)&pCount, g_count);
    cudaGetSymbolAddress((void**)&pCursor, g_cursor);

    cudaFuncSetAttribute(gemm_kernel,
                         cudaFuncAttributeMaxDynamicSharedMemorySize, GEMM_SMEM);

    int nchunk = (n + 1023) / 1024;
    int gemm_grid = (n + GEMM_BM - 1) / GEMM_BM;
    int warp_grid = (n + 7) / 8;

    // nodes 1-5
    cudaMemsetAsync(pCount, 0, n * sizeof(int));
    cudaMemsetAsync(pCursor, 0, n * sizeof(int));
    init_kernel<<<1, 32>>>(n, e);
    count_kernel<<<(e + 255) / 256, 256>>>(dst, e);
    dis_kernel<<<(n + 255) / 256, 256>>>(n);

    // node 6: layer-1 GEMM (profiled)
    gemm_kernel<<<gemm_grid, 256, GEMM_SMEM>>>(x, W1, pA, pDis, n);

    // CSR build
    scan1_kernel<<<nchunk, 256>>>(n);
    scan2_kernel<<<1, NCHUNK_MAX>>>(nchunk);
    scan3_kernel<<<nchunk, 256>>>(n);
    fill_kernel<<<(e + 255) / 256, 256>>>(src, dst, e);

    // layer 1 aggregation
    agg_kernel<<<warp_grid, 256>>>(pA, pB, b1, n);
    // layer 2
    gemm_kernel<<<gemm_grid, 256, GEMM_SMEM>>>(pB, W2, pA, pDis, n);
    agg_kernel<<<warp_grid, 256>>>(pA, pB, b2, n);
    // layer 3
    gemv_kernel<<<warp_grid, 256>>>(pB, W3, pS, n);
    agg3_kernel<<<(n + 255) / 256, 256>>>(pS, out, b3, n);
}